// round 1
// baseline (speedup 1.0000x reference)
#include <cuda_runtime.h>
#include <math.h>

#define IN_DIM 64
#define HID    128
#define OUTD   128
#define TILE   128
#define THREADS 256
#define WS     132          // padded smem stride for transposed weights (float4-aligned)
#define MAXN   100000

// scratch for precomputed node projections (allocation-free rule: __device__ globals)
__device__ float g_src_proj[(size_t)MAXN * HID];
__device__ float g_dst_proj[(size_t)MAXN * HID];

__device__ __forceinline__ float fsilu(float x) {
    return x / (1.0f + __expf(-x));
}

// ---------------------------------------------------------------------------
// Kernel 1: node projections.  blockIdx.y==0 -> src (no bias), ==1 -> dst (+b1)
// ---------------------------------------------------------------------------
__global__ __launch_bounds__(THREADS) void node_proj_kernel(
    const float* __restrict__ src_feat, const float* __restrict__ dst_feat,
    const float* __restrict__ W_src, const float* __restrict__ W_dst,
    const float* __restrict__ b1, int Nn)
{
    extern __shared__ float sm[];
    float* sW = sm;                    // IN_DIM * WS
    float* sX = sm + IN_DIM * WS;      // TILE * IN_DIM

    const int tid = threadIdx.x;
    const bool is_dst = (blockIdx.y == 1);
    const float* W = is_dst ? W_dst : W_src;
    const float* X = is_dst ? dst_feat : src_feat;
    float* Out = is_dst ? g_dst_proj : g_src_proj;
    const int n0 = blockIdx.x * TILE;

    // W [HID][IN] -> sW[k*WS + c] (transposed)
    for (int i = tid; i < HID * IN_DIM; i += THREADS) {
        int c = i >> 6, k = i & 63;
        sW[k * WS + c] = W[i];
    }
    // X tile (float4)
    for (int i = tid; i < TILE * (IN_DIM / 4); i += THREADS) {
        int nl = i >> 4, q = i & 15;
        int gn = n0 + nl; if (gn >= Nn) gn = Nn - 1;
        ((float4*)sX)[nl * 16 + q] = ((const float4*)X)[(size_t)gn * 16 + q];
    }
    __syncthreads();

    const int warp = tid >> 5, lane = tid & 31;
    const int c0 = lane * 4;
    const int eb = warp * 16;

    float acc[16][4];
    #pragma unroll
    for (int e = 0; e < 16; e++) { acc[e][0]=0.f; acc[e][1]=0.f; acc[e][2]=0.f; acc[e][3]=0.f; }

    #pragma unroll 2
    for (int k = 0; k < IN_DIM; k += 4) {
        float4 w0 = *(const float4*)&sW[(k + 0) * WS + c0];
        float4 w1 = *(const float4*)&sW[(k + 1) * WS + c0];
        float4 w2 = *(const float4*)&sW[(k + 2) * WS + c0];
        float4 w3 = *(const float4*)&sW[(k + 3) * WS + c0];
        #pragma unroll
        for (int e = 0; e < 16; e++) {
            float4 a = *(const float4*)&sX[(eb + e) * IN_DIM + k];
            acc[e][0] = fmaf(a.x, w0.x, fmaf(a.y, w1.x, fmaf(a.z, w2.x, fmaf(a.w, w3.x, acc[e][0]))));
            acc[e][1] = fmaf(a.x, w0.y, fmaf(a.y, w1.y, fmaf(a.z, w2.y, fmaf(a.w, w3.y, acc[e][1]))));
            acc[e][2] = fmaf(a.x, w0.z, fmaf(a.y, w1.z, fmaf(a.z, w2.z, fmaf(a.w, w3.z, acc[e][2]))));
            acc[e][3] = fmaf(a.x, w0.w, fmaf(a.y, w1.w, fmaf(a.z, w2.w, fmaf(a.w, w3.w, acc[e][3]))));
        }
    }

    float4 bias = make_float4(0.f, 0.f, 0.f, 0.f);
    if (is_dst) bias = *(const float4*)&b1[c0];

    #pragma unroll
    for (int e = 0; e < 16; e++) {
        int gn = n0 + eb + e;
        if (gn < Nn) {
            float4 o;
            o.x = acc[e][0] + bias.x;
            o.y = acc[e][1] + bias.y;
            o.z = acc[e][2] + bias.z;
            o.w = acc[e][3] + bias.w;
            *(float4*)&Out[(size_t)gn * HID + c0] = o;
        }
    }
}

// ---------------------------------------------------------------------------
// Kernel 2: fused edge pipeline
//   h = efeat@We^T + gather(p_src) + gather(p_dst); silu; out = LN(h@Wo^T + b)
// ---------------------------------------------------------------------------
__global__ __launch_bounds__(THREADS, 1) void edge_kernel(
    const float* __restrict__ efeat,
    const int* __restrict__ src_idx, const int* __restrict__ dst_idx,
    const float* __restrict__ W_efeat, const float* __restrict__ W_out,
    const float* __restrict__ b_out, const float* __restrict__ gamma,
    const float* __restrict__ beta,
    float* __restrict__ out, int E)
{
    extern __shared__ float sm[];
    float* sWe = sm;                               // 64*WS  = 8448
    float* sWo = sm + IN_DIM * WS;                 // 128*WS = 16896
    float* sE  = sWo + HID * WS;                   // 128*64 = 8192
    float* sH  = sE + TILE * IN_DIM;               // 128*128 = 16384
    int*   sSi = (int*)(sH + TILE * HID);          // 128
    int*   sDi = sSi + TILE;                       // 128

    const int tid = threadIdx.x;
    const int e0 = blockIdx.x * TILE;

    // W_efeat [HID][IN] -> sWe[k*WS + c]
    for (int i = tid; i < HID * IN_DIM; i += THREADS) {
        int c = i >> 6, k = i & 63;
        sWe[k * WS + c] = W_efeat[i];
    }
    // W_out [OUT][HID] -> sWo[k*WS + c]
    for (int i = tid; i < OUTD * HID; i += THREADS) {
        int c = i >> 7, k = i & 127;
        sWo[k * WS + c] = W_out[i];
    }
    // efeat tile
    for (int i = tid; i < TILE * (IN_DIM / 4); i += THREADS) {
        int el = i >> 4, q = i & 15;
        int ge = e0 + el; if (ge >= E) ge = E - 1;
        ((float4*)sE)[i] = ((const float4*)efeat)[(size_t)ge * 16 + q];
    }
    // indices
    if (tid < TILE) {
        int ge = e0 + tid;
        sSi[tid] = (ge < E) ? src_idx[ge] : 0;
    } else {
        int t = tid - TILE;
        int ge = e0 + t;
        sDi[t] = (ge < E) ? dst_idx[ge] : 0;
    }
    __syncthreads();

    const int warp = tid >> 5, lane = tid & 31;
    const int c0 = lane * 4;
    const int eb = warp * 16;

    // ---- phase 1: efeat @ We^T ----
    float acc[16][4];
    #pragma unroll
    for (int e = 0; e < 16; e++) { acc[e][0]=0.f; acc[e][1]=0.f; acc[e][2]=0.f; acc[e][3]=0.f; }

    #pragma unroll 2
    for (int k = 0; k < IN_DIM; k += 4) {
        float4 w0 = *(const float4*)&sWe[(k + 0) * WS + c0];
        float4 w1 = *(const float4*)&sWe[(k + 1) * WS + c0];
        float4 w2 = *(const float4*)&sWe[(k + 2) * WS + c0];
        float4 w3 = *(const float4*)&sWe[(k + 3) * WS + c0];
        #pragma unroll
        for (int e = 0; e < 16; e++) {
            float4 a = *(const float4*)&sE[(eb + e) * IN_DIM + k];
            acc[e][0] = fmaf(a.x, w0.x, fmaf(a.y, w1.x, fmaf(a.z, w2.x, fmaf(a.w, w3.x, acc[e][0]))));
            acc[e][1] = fmaf(a.x, w0.y, fmaf(a.y, w1.y, fmaf(a.z, w2.y, fmaf(a.w, w3.y, acc[e][1]))));
            acc[e][2] = fmaf(a.x, w0.z, fmaf(a.y, w1.z, fmaf(a.z, w2.z, fmaf(a.w, w3.z, acc[e][2]))));
            acc[e][3] = fmaf(a.x, w0.w, fmaf(a.y, w1.w, fmaf(a.z, w2.w, fmaf(a.w, w3.w, acc[e][3]))));
        }
    }

    // ---- gather node projections, add, silu, stage h ----
    #pragma unroll
    for (int e = 0; e < 16; e++) {
        int si = sSi[eb + e];
        int di = sDi[eb + e];
        float4 ps = *(const float4*)&g_src_proj[(size_t)si * HID + c0];
        float4 pd = *(const float4*)&g_dst_proj[(size_t)di * HID + c0];
        float4 h;
        h.x = fsilu(acc[e][0] + ps.x + pd.x);
        h.y = fsilu(acc[e][1] + ps.y + pd.y);
        h.z = fsilu(acc[e][2] + ps.z + pd.z);
        h.w = fsilu(acc[e][3] + ps.w + pd.w);
        *(float4*)&sH[(eb + e) * HID + c0] = h;
    }
    __syncthreads();

    // ---- phase 2: h @ Wo^T ----
    float acc2[16][4];
    #pragma unroll
    for (int e = 0; e < 16; e++) { acc2[e][0]=0.f; acc2[e][1]=0.f; acc2[e][2]=0.f; acc2[e][3]=0.f; }

    #pragma unroll 2
    for (int k = 0; k < HID; k += 4) {
        float4 w0 = *(const float4*)&sWo[(k + 0) * WS + c0];
        float4 w1 = *(const float4*)&sWo[(k + 1) * WS + c0];
        float4 w2 = *(const float4*)&sWo[(k + 2) * WS + c0];
        float4 w3 = *(const float4*)&sWo[(k + 3) * WS + c0];
        #pragma unroll
        for (int e = 0; e < 16; e++) {
            float4 a = *(const float4*)&sH[(eb + e) * HID + k];
            acc2[e][0] = fmaf(a.x, w0.x, fmaf(a.y, w1.x, fmaf(a.z, w2.x, fmaf(a.w, w3.x, acc2[e][0]))));
            acc2[e][1] = fmaf(a.x, w0.y, fmaf(a.y, w1.y, fmaf(a.z, w2.y, fmaf(a.w, w3.y, acc2[e][1]))));
            acc2[e][2] = fmaf(a.x, w0.z, fmaf(a.y, w1.z, fmaf(a.z, w2.z, fmaf(a.w, w3.z, acc2[e][2]))));
            acc2[e][3] = fmaf(a.x, w0.w, fmaf(a.y, w1.w, fmaf(a.z, w2.w, fmaf(a.w, w3.w, acc2[e][3]))));
        }
    }

    // ---- bias + layernorm + store ----
    float4 bo = *(const float4*)&b_out[c0];
    float4 ga = *(const float4*)&gamma[c0];
    float4 be = *(const float4*)&beta[c0];

    #pragma unroll
    for (int e = 0; e < 16; e++) {
        float v0 = acc2[e][0] + bo.x;
        float v1 = acc2[e][1] + bo.y;
        float v2 = acc2[e][2] + bo.z;
        float v3 = acc2[e][3] + bo.w;
        float s  = v0 + v1 + v2 + v3;
        float ss = v0*v0 + v1*v1 + v2*v2 + v3*v3;
        #pragma unroll
        for (int o = 16; o > 0; o >>= 1) {
            s  += __shfl_xor_sync(0xffffffffu, s,  o);
            ss += __shfl_xor_sync(0xffffffffu, ss, o);
        }
        float mean = s * (1.0f / OUTD);
        float var  = ss * (1.0f / OUTD) - mean * mean;
        float inv  = rsqrtf(var + 1e-5f);
        float4 r;
        r.x = (v0 - mean) * inv * ga.x + be.x;
        r.y = (v1 - mean) * inv * ga.y + be.y;
        r.z = (v2 - mean) * inv * ga.z + be.z;
        r.w = (v3 - mean) * inv * ga.w + be.w;
        int ge = e0 + eb + e;
        if (ge < E) *(float4*)&out[(size_t)ge * OUTD + c0] = r;
    }
}

// ---------------------------------------------------------------------------
extern "C" void kernel_launch(void* const* d_in, const int* in_sizes, int n_in,
                              void* d_out, int out_size)
{
    const float* efeat    = (const float*)d_in[0];
    const float* src_feat = (const float*)d_in[1];
    const float* dst_feat = (const float*)d_in[2];
    const int*   src_idx  = (const int*)d_in[3];
    const int*   dst_idx  = (const int*)d_in[4];
    const float* W_efeat  = (const float*)d_in[5];
    const float* W_src    = (const float*)d_in[6];
    const float* W_dst    = (const float*)d_in[7];
    const float* b1       = (const float*)d_in[8];
    const float* W_out    = (const float*)d_in[9];
    const float* b_out    = (const float*)d_in[10];
    const float* ln_gamma = (const float*)d_in[11];
    const float* ln_beta  = (const float*)d_in[12];
    float* out = (float*)d_out;

    const int E  = in_sizes[0] / IN_DIM;
    const int Nn = in_sizes[1] / IN_DIM;

    const size_t smem_node = (size_t)(IN_DIM * WS + TILE * IN_DIM) * sizeof(float);
    const size_t smem_edge = (size_t)(IN_DIM * WS + HID * WS + TILE * IN_DIM + TILE * HID) * sizeof(float)
                           + 2 * TILE * sizeof(int);

    cudaFuncSetAttribute(node_proj_kernel, cudaFuncAttributeMaxDynamicSharedMemorySize, (int)smem_node);
    cudaFuncSetAttribute(edge_kernel,      cudaFuncAttributeMaxDynamicSharedMemorySize, (int)smem_edge);

    dim3 gn((Nn + TILE - 1) / TILE, 2);
    node_proj_kernel<<<gn, THREADS, smem_node>>>(src_feat, dst_feat, W_src, W_dst, b1, Nn);

    int gb = (E + TILE - 1) / TILE;
    edge_kernel<<<gb, THREADS, smem_edge>>>(efeat, src_idx, dst_idx, W_efeat, W_out,
                                            b_out, ln_gamma, ln_beta, out, E);
}

// round 5
// speedup vs baseline: 2.4312x; 2.4312x over previous
#include <cuda_runtime.h>
#include <cuda_bf16.h>
#include <stdint.h>
#include <math.h>

#define IN_DIM 64
#define HID    128
#define OUTD   128
#define TILE   128
#define MAXN   100000

// ------------------------- scratch (no-alloc rule) --------------------------
__device__ float g_src_proj[(size_t)MAXN * HID];
__device__ float g_dst_proj[(size_t)MAXN * HID];

// ------------------------- helpers ------------------------------------------
__device__ __forceinline__ uint32_t smem_u32(const void* p) {
    uint32_t a;
    asm("{ .reg .u64 t; cvta.to.shared.u64 t, %1; cvt.u32.u64 %0, t; }" : "=r"(a) : "l"(p));
    return a;
}
__device__ __forceinline__ void ldsm4(uint32_t* r, uint32_t addr) {
    asm volatile("ldmatrix.sync.aligned.m8n8.x4.shared.b16 {%0,%1,%2,%3}, [%4];"
                 : "=r"(r[0]), "=r"(r[1]), "=r"(r[2]), "=r"(r[3]) : "r"(addr));
}
__device__ __forceinline__ void mma16816(float* d, const uint32_t* a, const uint32_t* b) {
    asm volatile("mma.sync.aligned.m16n8k16.row.col.f32.bf16.bf16.f32 "
                 "{%0,%1,%2,%3}, {%4,%5,%6,%7}, {%8,%9}, {%0,%1,%2,%3};"
                 : "+f"(d[0]), "+f"(d[1]), "+f"(d[2]), "+f"(d[3])
                 : "r"(a[0]), "r"(a[1]), "r"(a[2]), "r"(a[3]), "r"(b[0]), "r"(b[1]));
}
__device__ __forceinline__ void split_pack(float x, float y, uint32_t& h, uint32_t& l) {
    __nv_bfloat16 xh = __float2bfloat16(x), yh = __float2bfloat16(y);
    __nv_bfloat16 xl = __float2bfloat16(x - __bfloat162float(xh));
    __nv_bfloat16 yl = __float2bfloat16(y - __bfloat162float(yh));
    h = (uint32_t)(*(uint16_t*)&xh) | ((uint32_t)(*(uint16_t*)&yh) << 16);
    l = (uint32_t)(*(uint16_t*)&xl) | ((uint32_t)(*(uint16_t*)&yl) << 16);
}
__device__ __forceinline__ float fsilu(float x) { return x / (1.0f + __expf(-x)); }

// ------------------------- smem layout (edge kernel) ------------------------
// W1 (GEMM1 B): [128 n][72 bf16] stride 144B (pad 8)  -> conflict-free ldmatrix
// W2 (GEMM2 B): [128 n][136 bf16] stride 272B (pad 8)
#define W1_STRIDE 72
#define W2_STRIDE 136
#define OFF_W1H 0
#define OFF_W1L 18432
#define OFF_W2H 36864
#define OFF_W2L 71680
#define OFF_BO  106496
#define OFF_GA  107008
#define OFF_BE  107520
#define SMEM_EDGE_BYTES 108032

// ---------------------------------------------------------------------------
// Kernel 1: node projections (SIMT fp32, exact)
// ---------------------------------------------------------------------------
#define WS 132
__global__ __launch_bounds__(256) void node_proj_kernel(
    const float* __restrict__ src_feat, const float* __restrict__ dst_feat,
    const float* __restrict__ W_src, const float* __restrict__ W_dst,
    const float* __restrict__ b1, int Nn)
{
    extern __shared__ float sm[];
    float* sW = sm;
    float* sX = sm + IN_DIM * WS;
    const int tid = threadIdx.x;
    const bool is_dst = (blockIdx.y == 1);
    const float* W = is_dst ? W_dst : W_src;
    const float* X = is_dst ? dst_feat : src_feat;
    float* Out = is_dst ? g_dst_proj : g_src_proj;
    const int n0 = blockIdx.x * TILE;

    for (int i = tid; i < HID * IN_DIM; i += 256) {
        int c = i >> 6, k = i & 63;
        sW[k * WS + c] = W[i];
    }
    for (int i = tid; i < TILE * (IN_DIM / 4); i += 256) {
        int nl = i >> 4, q = i & 15;
        int gn = n0 + nl; if (gn >= Nn) gn = Nn - 1;
        ((float4*)sX)[nl * 16 + q] = ((const float4*)X)[(size_t)gn * 16 + q];
    }
    __syncthreads();

    const int warp = tid >> 5, lane = tid & 31;
    const int c0 = lane * 4;
    const int eb = warp * 16;
    float acc[16][4];
    #pragma unroll
    for (int e = 0; e < 16; e++) { acc[e][0]=0.f; acc[e][1]=0.f; acc[e][2]=0.f; acc[e][3]=0.f; }
    #pragma unroll 2
    for (int k = 0; k < IN_DIM; k += 4) {
        float4 w0 = *(const float4*)&sW[(k + 0) * WS + c0];
        float4 w1 = *(const float4*)&sW[(k + 1) * WS + c0];
        float4 w2 = *(const float4*)&sW[(k + 2) * WS + c0];
        float4 w3 = *(const float4*)&sW[(k + 3) * WS + c0];
        #pragma unroll
        for (int e = 0; e < 16; e++) {
            float4 a = *(const float4*)&sX[(eb + e) * IN_DIM + k];
            acc[e][0] = fmaf(a.x, w0.x, fmaf(a.y, w1.x, fmaf(a.z, w2.x, fmaf(a.w, w3.x, acc[e][0]))));
            acc[e][1] = fmaf(a.x, w0.y, fmaf(a.y, w1.y, fmaf(a.z, w2.y, fmaf(a.w, w3.y, acc[e][1]))));
            acc[e][2] = fmaf(a.x, w0.z, fmaf(a.y, w1.z, fmaf(a.z, w2.z, fmaf(a.w, w3.z, acc[e][2]))));
            acc[e][3] = fmaf(a.x, w0.w, fmaf(a.y, w1.w, fmaf(a.z, w2.w, fmaf(a.w, w3.w, acc[e][3]))));
        }
    }
    float4 bias = make_float4(0.f, 0.f, 0.f, 0.f);
    if (is_dst) bias = *(const float4*)&b1[c0];
    #pragma unroll
    for (int e = 0; e < 16; e++) {
        int gn = n0 + eb + e;
        if (gn < Nn) {
            float4 o;
            o.x = acc[e][0] + bias.x; o.y = acc[e][1] + bias.y;
            o.z = acc[e][2] + bias.z; o.w = acc[e][3] + bias.w;
            *(float4*)&Out[(size_t)gn * HID + c0] = o;
        }
    }
}

// ---------------------------------------------------------------------------
// Kernel 2: persistent HMMA (mma.sync bf16 split-2) edge pipeline
// ---------------------------------------------------------------------------
__global__ __launch_bounds__(256, 1) void edge_mma_kernel(
    const float* __restrict__ efeat,
    const int* __restrict__ src_idx, const int* __restrict__ dst_idx,
    const float* __restrict__ W_efeat, const float* __restrict__ W_out,
    const float* __restrict__ b_out, const float* __restrict__ gamma,
    const float* __restrict__ beta,
    float* __restrict__ out, int E, int ntiles)
{
    extern __shared__ char smraw[];
    char* sm = smraw;
    const uint32_t base = smem_u32(smraw);
    const int tid = threadIdx.x;

    __nv_bfloat16* sW1H = (__nv_bfloat16*)(sm + OFF_W1H);
    __nv_bfloat16* sW1L = (__nv_bfloat16*)(sm + OFF_W1L);
    __nv_bfloat16* sW2H = (__nv_bfloat16*)(sm + OFF_W2H);
    __nv_bfloat16* sW2L = (__nv_bfloat16*)(sm + OFF_W2L);
    float* sBO = (float*)(sm + OFF_BO);
    float* sGA = (float*)(sm + OFF_GA);
    float* sBE = (float*)(sm + OFF_BE);

    // ---- stage weights (hi/lo split) ----
    for (int i = tid; i < HID * (IN_DIM / 2); i += 256) {   // 4096 float2
        int n = i >> 5, p = i & 31;
        float2 f = ((const float2*)W_efeat)[n * 32 + p];
        __nv_bfloat16 xh = __float2bfloat16(f.x), yh = __float2bfloat16(f.y);
        sW1H[n * W1_STRIDE + 2 * p]     = xh;
        sW1H[n * W1_STRIDE + 2 * p + 1] = yh;
        sW1L[n * W1_STRIDE + 2 * p]     = __float2bfloat16(f.x - __bfloat162float(xh));
        sW1L[n * W1_STRIDE + 2 * p + 1] = __float2bfloat16(f.y - __bfloat162float(yh));
    }
    for (int i = tid; i < OUTD * (HID / 2); i += 256) {     // 8192 float2
        int n = i >> 6, p = i & 63;
        float2 f = ((const float2*)W_out)[n * 64 + p];
        __nv_bfloat16 xh = __float2bfloat16(f.x), yh = __float2bfloat16(f.y);
        sW2H[n * W2_STRIDE + 2 * p]     = xh;
        sW2H[n * W2_STRIDE + 2 * p + 1] = yh;
        sW2L[n * W2_STRIDE + 2 * p]     = __float2bfloat16(f.x - __bfloat162float(xh));
        sW2L[n * W2_STRIDE + 2 * p + 1] = __float2bfloat16(f.y - __bfloat162float(yh));
    }
    if (tid < 128) {
        sBO[tid] = b_out[tid];
        sGA[tid] = gamma[tid];
        sBE[tid] = beta[tid];
    }
    __syncthreads();

    const int lane = tid & 31, warp = tid >> 5;
    const int qrow = lane >> 2, qcol = lane & 3;
    // ldmatrix lane address components: g=lane/8, r=lane%8
    const int g = lane >> 3, r = lane & 7;
    const int lro = ((g & 2) ? 8 : 0) + r;   // row offset within 16-row tile
    const int lco = (g & 1) * 8;             // k offset (0 or 8)
    const uint32_t w1h_base = base + OFF_W1H + (uint32_t)(lro * W1_STRIDE + lco) * 2;
    const uint32_t w1l_base = base + OFF_W1L + (uint32_t)(lro * W1_STRIDE + lco) * 2;
    const uint32_t w2h_base = base + OFF_W2H + (uint32_t)(lro * W2_STRIDE + lco) * 2;
    const uint32_t w2l_base = base + OFF_W2L + (uint32_t)(lro * W2_STRIDE + lco) * 2;

    for (int tile = blockIdx.x; tile < ntiles; tile += gridDim.x) {
        const int e0w = tile * TILE + warp * 16;
        const int er0i = e0w + qrow, er1i = er0i + 8;
        const int ge0 = (er0i < E) ? er0i : (E - 1);
        const int ge1 = (er1i < E) ? er1i : (E - 1);
        const float* er0 = efeat + (size_t)ge0 * IN_DIM + 2 * qcol;
        const float* er1 = efeat + (size_t)ge1 * IN_DIM + 2 * qcol;

        // ---- A1 fragments straight from global ----
        uint32_t aH1[4][4], aL1[4][4];
        #pragma unroll
        for (int s = 0; s < 4; s++) {
            float2 f0 = *(const float2*)(er0 + 16 * s);
            float2 f1 = *(const float2*)(er1 + 16 * s);
            float2 f2 = *(const float2*)(er0 + 16 * s + 8);
            float2 f3 = *(const float2*)(er1 + 16 * s + 8);
            split_pack(f0.x, f0.y, aH1[s][0], aL1[s][0]);
            split_pack(f1.x, f1.y, aH1[s][1], aL1[s][1]);
            split_pack(f2.x, f2.y, aH1[s][2], aL1[s][2]);
            split_pack(f3.x, f3.y, aH1[s][3], aL1[s][3]);
        }

        // ---- GEMM1: 128x128x64, 3-term split ----
        float acc1[16][4];
        #pragma unroll
        for (int j = 0; j < 16; j++) { acc1[j][0]=0.f; acc1[j][1]=0.f; acc1[j][2]=0.f; acc1[j][3]=0.f; }
        #pragma unroll
        for (int s = 0; s < 4; s++) {
            #pragma unroll
            for (int jp = 0; jp < 8; jp++) {
                uint32_t off = (uint32_t)(jp * 16 * W1_STRIDE + 16 * s) * 2;
                uint32_t bh[4], bl[4];
                ldsm4(bh, w1h_base + off);
                ldsm4(bl, w1l_base + off);
                mma16816(acc1[2*jp],   aH1[s], bh);
                mma16816(acc1[2*jp+1], aH1[s], bh + 2);
                mma16816(acc1[2*jp],   aH1[s], bl);
                mma16816(acc1[2*jp+1], aH1[s], bl + 2);
                mma16816(acc1[2*jp],   aL1[s], bh);
                mma16816(acc1[2*jp+1], aL1[s], bh + 2);
            }
        }

        // ---- gather node projections + SiLU (in registers) ----
        const int si0 = src_idx[ge0], di0 = dst_idx[ge0];
        const int si1 = src_idx[ge1], di1 = dst_idx[ge1];
        const float* ps0 = g_src_proj + (size_t)si0 * HID + 2 * qcol;
        const float* pd0 = g_dst_proj + (size_t)di0 * HID + 2 * qcol;
        const float* ps1 = g_src_proj + (size_t)si1 * HID + 2 * qcol;
        const float* pd1 = g_dst_proj + (size_t)di1 * HID + 2 * qcol;
        #pragma unroll
        for (int j = 0; j < 16; j++) {
            float2 a = *(const float2*)(ps0 + 8 * j);
            float2 b = *(const float2*)(pd0 + 8 * j);
            float2 c = *(const float2*)(ps1 + 8 * j);
            float2 d = *(const float2*)(pd1 + 8 * j);
            acc1[j][0] = fsilu(acc1[j][0] + a.x + b.x);
            acc1[j][1] = fsilu(acc1[j][1] + a.y + b.y);
            acc1[j][2] = fsilu(acc1[j][2] + c.x + d.x);
            acc1[j][3] = fsilu(acc1[j][3] + c.y + d.y);
        }

        // ---- GEMM2: 128x128x128, A-frags built from acc1 (D-frag == A-frag) ----
        float acc2[16][4];
        #pragma unroll
        for (int j = 0; j < 16; j++) { acc2[j][0]=0.f; acc2[j][1]=0.f; acc2[j][2]=0.f; acc2[j][3]=0.f; }
        #pragma unroll
        for (int s = 0; s < 8; s++) {
            uint32_t aH2[4], aL2[4];
            split_pack(acc1[2*s][0],   acc1[2*s][1],   aH2[0], aL2[0]);
            split_pack(acc1[2*s][2],   acc1[2*s][3],   aH2[1], aL2[1]);
            split_pack(acc1[2*s+1][0], acc1[2*s+1][1], aH2[2], aL2[2]);
            split_pack(acc1[2*s+1][2], acc1[2*s+1][3], aH2[3], aL2[3]);
            #pragma unroll
            for (int jp = 0; jp < 8; jp++) {
                uint32_t off = (uint32_t)(jp * 16 * W2_STRIDE + 16 * s) * 2;
                uint32_t bh[4], bl[4];
                ldsm4(bh, w2h_base + off);
                ldsm4(bl, w2l_base + off);
                mma16816(acc2[2*jp],   aH2, bh);
                mma16816(acc2[2*jp+1], aH2, bh + 2);
                mma16816(acc2[2*jp],   aH2, bl);
                mma16816(acc2[2*jp+1], aH2, bl + 2);
                mma16816(acc2[2*jp],   aL2, bh);
                mma16816(acc2[2*jp+1], aL2, bh + 2);
            }
        }

        // ---- bias + LayerNorm (quad shuffle) + store ----
        float s0 = 0.f, ss0 = 0.f, s1 = 0.f, ss1 = 0.f;
        #pragma unroll
        for (int j = 0; j < 16; j++) {
            float2 bo = *(const float2*)(sBO + 8 * j + 2 * qcol);
            acc2[j][0] += bo.x; acc2[j][1] += bo.y;
            acc2[j][2] += bo.x; acc2[j][3] += bo.y;
            s0  += acc2[j][0] + acc2[j][1];
            ss0 += acc2[j][0] * acc2[j][0] + acc2[j][1] * acc2[j][1];
            s1  += acc2[j][2] + acc2[j][3];
            ss1 += acc2[j][2] * acc2[j][2] + acc2[j][3] * acc2[j][3];
        }
        s0  += __shfl_xor_sync(0xffffffffu, s0, 1);  s0  += __shfl_xor_sync(0xffffffffu, s0, 2);
        ss0 += __shfl_xor_sync(0xffffffffu, ss0, 1); ss0 += __shfl_xor_sync(0xffffffffu, ss0, 2);
        s1  += __shfl_xor_sync(0xffffffffu, s1, 1);  s1  += __shfl_xor_sync(0xffffffffu, s1, 2);
        ss1 += __shfl_xor_sync(0xffffffffu, ss1, 1); ss1 += __shfl_xor_sync(0xffffffffu, ss1, 2);

        const float m0 = s0 * (1.0f / OUTD);
        const float v0 = ss0 * (1.0f / OUTD) - m0 * m0;
        const float i0 = rsqrtf(v0 + 1e-5f);
        const float m1 = s1 * (1.0f / OUTD);
        const float v1 = ss1 * (1.0f / OUTD) - m1 * m1;
        const float i1 = rsqrtf(v1 + 1e-5f);

        const bool st0 = (er0i < E), st1 = (er1i < E);
        float* o0 = out + (size_t)er0i * OUTD + 2 * qcol;
        float* o1 = out + (size_t)er1i * OUTD + 2 * qcol;
        #pragma unroll
        for (int j = 0; j < 16; j++) {
            float2 ga = *(const float2*)(sGA + 8 * j + 2 * qcol);
            float2 be = *(const float2*)(sBE + 8 * j + 2 * qcol);
            if (st0) {
                float2 w;
                w.x = (acc2[j][0] - m0) * i0 * ga.x + be.x;
                w.y = (acc2[j][1] - m0) * i0 * ga.y + be.y;
                *(float2*)(o0 + 8 * j) = w;
            }
            if (st1) {
                float2 w;
                w.x = (acc2[j][2] - m1) * i1 * ga.x + be.x;
                w.y = (acc2[j][3] - m1) * i1 * ga.y + be.y;
                *(float2*)(o1 + 8 * j) = w;
            }
        }
    }
}

// ---------------------------------------------------------------------------
extern "C" void kernel_launch(void* const* d_in, const int* in_sizes, int n_in,
                              void* d_out, int out_size)
{
    const float* efeat    = (const float*)d_in[0];
    const float* src_feat = (const float*)d_in[1];
    const float* dst_feat = (const float*)d_in[2];
    const int*   src_idx  = (const int*)d_in[3];
    const int*   dst_idx  = (const int*)d_in[4];
    const float* W_efeat  = (const float*)d_in[5];
    const float* W_src    = (const float*)d_in[6];
    const float* W_dst    = (const float*)d_in[7];
    const float* b1       = (const float*)d_in[8];
    const float* W_out    = (const float*)d_in[9];
    const float* b_out    = (const float*)d_in[10];
    const float* ln_gamma = (const float*)d_in[11];
    const float* ln_beta  = (const float*)d_in[12];
    float* out = (float*)d_out;

    const int E  = in_sizes[0] / IN_DIM;
    const int Nn = in_sizes[1] / IN_DIM;
    const int ntiles = (E + TILE - 1) / TILE;

    const size_t smem_node = (size_t)(IN_DIM * WS + TILE * IN_DIM) * sizeof(float);
    cudaFuncSetAttribute(node_proj_kernel, cudaFuncAttributeMaxDynamicSharedMemorySize, (int)smem_node);
    cudaFuncSetAttribute(edge_mma_kernel, cudaFuncAttributeMaxDynamicSharedMemorySize, SMEM_EDGE_BYTES);

    int nsm = 148;
    cudaDeviceGetAttribute(&nsm, cudaDevAttrMultiProcessorCount, 0);

    dim3 gn((Nn + TILE - 1) / TILE, 2);
    node_proj_kernel<<<gn, 256, smem_node>>>(src_feat, dst_feat, W_src, W_dst, b1, Nn);

    int grid = (ntiles < nsm) ? ntiles : nsm;
    edge_mma_kernel<<<grid, 256, SMEM_EDGE_BYTES>>>(efeat, src_idx, dst_idx, W_efeat, W_out,
                                                    b_out, ln_gamma, ln_beta, out, E, ntiles);
}

// round 6
// speedup vs baseline: 2.7576x; 1.1342x over previous
#include <cuda_runtime.h>
#include <cuda_bf16.h>
#include <stdint.h>
#include <math.h>

#define IN_DIM 64
#define HID    128
#define OUTD   128
#define TILE   128
#define MAXN   100000

// ------------------------- scratch (no-alloc rule) --------------------------
__device__ float g_src_proj[(size_t)MAXN * HID];
__device__ float g_dst_proj[(size_t)MAXN * HID];

// ------------------------- helpers ------------------------------------------
__device__ __forceinline__ uint32_t smem_u32(const void* p) {
    uint32_t a;
    asm("{ .reg .u64 t; cvta.to.shared.u64 t, %1; cvt.u32.u64 %0, t; }" : "=r"(a) : "l"(p));
    return a;
}
__device__ __forceinline__ void ldsm4(uint32_t* r, uint32_t addr) {
    asm volatile("ldmatrix.sync.aligned.m8n8.x4.shared.b16 {%0,%1,%2,%3}, [%4];"
                 : "=r"(r[0]), "=r"(r[1]), "=r"(r[2]), "=r"(r[3]) : "r"(addr));
}
__device__ __forceinline__ void mma16816(float* d, const uint32_t* a, const uint32_t* b) {
    asm volatile("mma.sync.aligned.m16n8k16.row.col.f32.bf16.bf16.f32 "
                 "{%0,%1,%2,%3}, {%4,%5,%6,%7}, {%8,%9}, {%0,%1,%2,%3};"
                 : "+f"(d[0]), "+f"(d[1]), "+f"(d[2]), "+f"(d[3])
                 : "r"(a[0]), "r"(a[1]), "r"(a[2]), "r"(a[3]), "r"(b[0]), "r"(b[1]));
}
__device__ __forceinline__ void split_pack(float x, float y, uint32_t& h, uint32_t& l) {
    __nv_bfloat16 xh = __float2bfloat16(x), yh = __float2bfloat16(y);
    __nv_bfloat16 xl = __float2bfloat16(x - __bfloat162float(xh));
    __nv_bfloat16 yl = __float2bfloat16(y - __bfloat162float(yh));
    h = (uint32_t)(*(uint16_t*)&xh) | ((uint32_t)(*(uint16_t*)&yh) << 16);
    l = (uint32_t)(*(uint16_t*)&xl) | ((uint32_t)(*(uint16_t*)&yl) << 16);
}
__device__ __forceinline__ float fsilu(float x) { return x / (1.0f + __expf(-x)); }

// ------------------------- smem layouts --------------------------------------
#define W1_STRIDE 72
#define W2_STRIDE 136
// edge kernel
#define OFF_W1H 0
#define OFF_W1L 18432
#define OFF_W2H 36864
#define OFF_W2L 71680
#define OFF_BO  106496
#define OFF_GA  107008
#define OFF_BE  107520
#define SMEM_EDGE_BYTES 108032
// node kernel: W_src hi/lo, W_dst hi/lo, b1
#define OFF_NSH 0
#define OFF_NSL 18432
#define OFF_NDH 36864
#define OFF_NDL 55296
#define OFF_NB1 73728
#define SMEM_NODE_BYTES 74240

// stage a [128 x 64] fp32 weight into hi/lo bf16 smem tiles (stride W1_STRIDE)
__device__ __forceinline__ void stage_w64(const float* __restrict__ W,
                                          __nv_bfloat16* sH, __nv_bfloat16* sL, int tid, int nthr) {
    for (int i = tid; i < HID * (IN_DIM / 2); i += nthr) {
        int n = i >> 5, p = i & 31;
        float2 f = ((const float2*)W)[n * 32 + p];
        __nv_bfloat16 xh = __float2bfloat16(f.x), yh = __float2bfloat16(f.y);
        sH[n * W1_STRIDE + 2 * p]     = xh;
        sH[n * W1_STRIDE + 2 * p + 1] = yh;
        sL[n * W1_STRIDE + 2 * p]     = __float2bfloat16(f.x - __bfloat162float(xh));
        sL[n * W1_STRIDE + 2 * p + 1] = __float2bfloat16(f.y - __bfloat162float(yh));
    }
}

// ---------------------------------------------------------------------------
// Kernel 1: node projections via HMMA (same GEMM1 structure as edge kernel)
// ---------------------------------------------------------------------------
__global__ __launch_bounds__(256) void node_mma_kernel(
    const float* __restrict__ src_feat, const float* __restrict__ dst_feat,
    const float* __restrict__ W_src, const float* __restrict__ W_dst,
    const float* __restrict__ b1, int Nn, int ntilesN)
{
    extern __shared__ char smraw[];
    char* sm = smraw;
    const uint32_t base = smem_u32(smraw);
    const int tid = threadIdx.x;

    stage_w64(W_src, (__nv_bfloat16*)(sm + OFF_NSH), (__nv_bfloat16*)(sm + OFF_NSL), tid, 256);
    stage_w64(W_dst, (__nv_bfloat16*)(sm + OFF_NDH), (__nv_bfloat16*)(sm + OFF_NDL), tid, 256);
    if (tid < 128) ((float*)(sm + OFF_NB1))[tid] = b1[tid];
    __syncthreads();

    const int lane = tid & 31, warp = tid >> 5;
    const int qrow = lane >> 2, qcol = lane & 3;
    const int g = lane >> 3, r = lane & 7;
    const int lro = ((g & 2) ? 8 : 0) + r;
    const int lco = (g & 1) * 8;
    const uint32_t lmoff = (uint32_t)(lro * W1_STRIDE + lco) * 2;

    const int nitems = 2 * ntilesN;
    for (int item = blockIdx.x; item < nitems; item += gridDim.x) {
        const bool is_dst = (item >= ntilesN);
        const int tile = is_dst ? (item - ntilesN) : item;
        const float* X = is_dst ? dst_feat : src_feat;
        float* Out = is_dst ? g_dst_proj : g_src_proj;
        const uint32_t wh_base = base + (is_dst ? OFF_NDH : OFF_NSH) + lmoff;
        const uint32_t wl_base = base + (is_dst ? OFF_NDL : OFF_NSL) + lmoff;

        const int n0w = tile * TILE + warp * 16;
        const int nr0i = n0w + qrow, nr1i = nr0i + 8;
        const int gn0 = (nr0i < Nn) ? nr0i : (Nn - 1);
        const int gn1 = (nr1i < Nn) ? nr1i : (Nn - 1);
        const float* xr0 = X + (size_t)gn0 * IN_DIM + 2 * qcol;
        const float* xr1 = X + (size_t)gn1 * IN_DIM + 2 * qcol;

        uint32_t aH[4][4], aL[4][4];
        #pragma unroll
        for (int s = 0; s < 4; s++) {
            float2 f0 = *(const float2*)(xr0 + 16 * s);
            float2 f1 = *(const float2*)(xr1 + 16 * s);
            float2 f2 = *(const float2*)(xr0 + 16 * s + 8);
            float2 f3 = *(const float2*)(xr1 + 16 * s + 8);
            split_pack(f0.x, f0.y, aH[s][0], aL[s][0]);
            split_pack(f1.x, f1.y, aH[s][1], aL[s][1]);
            split_pack(f2.x, f2.y, aH[s][2], aL[s][2]);
            split_pack(f3.x, f3.y, aH[s][3], aL[s][3]);
        }

        float acc[16][4];
        #pragma unroll
        for (int j = 0; j < 16; j++) { acc[j][0]=0.f; acc[j][1]=0.f; acc[j][2]=0.f; acc[j][3]=0.f; }

        #pragma unroll
        for (int s = 0; s < 4; s++) {
            uint32_t bH[8][4], bL[8][4];
            #pragma unroll
            for (int jp = 0; jp < 8; jp++)
                ldsm4(bH[jp], wh_base + (uint32_t)(jp * 16 * W1_STRIDE + 16 * s) * 2);
            #pragma unroll
            for (int jp = 0; jp < 8; jp++) {
                mma16816(acc[2*jp],   aH[s], bH[jp]);
                mma16816(acc[2*jp+1], aH[s], bH[jp] + 2);
            }
            #pragma unroll
            for (int jp = 0; jp < 8; jp++)
                ldsm4(bL[jp], wl_base + (uint32_t)(jp * 16 * W1_STRIDE + 16 * s) * 2);
            #pragma unroll
            for (int jp = 0; jp < 8; jp++) {
                mma16816(acc[2*jp],   aL[s], bH[jp]);
                mma16816(acc[2*jp+1], aL[s], bH[jp] + 2);
            }
            #pragma unroll
            for (int jp = 0; jp < 8; jp++) {
                mma16816(acc[2*jp],   aH[s], bL[jp]);
                mma16816(acc[2*jp+1], aH[s], bL[jp] + 2);
            }
        }

        const float* sb1 = (const float*)(sm + OFF_NB1);
        const bool st0 = (nr0i < Nn), st1 = (nr1i < Nn);
        float* o0 = Out + (size_t)nr0i * HID + 2 * qcol;
        float* o1 = Out + (size_t)nr1i * HID + 2 * qcol;
        #pragma unroll
        for (int j = 0; j < 16; j++) {
            float2 bb = make_float2(0.f, 0.f);
            if (is_dst) bb = *(const float2*)(sb1 + 8 * j + 2 * qcol);
            if (st0) *(float2*)(o0 + 8 * j) = make_float2(acc[j][0] + bb.x, acc[j][1] + bb.y);
            if (st1) *(float2*)(o1 + 8 * j) = make_float2(acc[j][2] + bb.x, acc[j][3] + bb.y);
        }
    }
}

// ---------------------------------------------------------------------------
// Kernel 2: persistent HMMA edge pipeline, batched MMA scheduling
// ---------------------------------------------------------------------------
__global__ __launch_bounds__(256) void edge_mma_kernel(
    const float* __restrict__ efeat,
    const int* __restrict__ src_idx, const int* __restrict__ dst_idx,
    const float* __restrict__ W_efeat, const float* __restrict__ W_out,
    const float* __restrict__ b_out, const float* __restrict__ gamma,
    const float* __restrict__ beta,
    float* __restrict__ out, int E, int ntiles)
{
    extern __shared__ char smraw[];
    char* sm = smraw;
    const uint32_t base = smem_u32(smraw);
    const int tid = threadIdx.x;

    stage_w64(W_efeat, (__nv_bfloat16*)(sm + OFF_W1H), (__nv_bfloat16*)(sm + OFF_W1L), tid, 256);
    {
        __nv_bfloat16* sW2H = (__nv_bfloat16*)(sm + OFF_W2H);
        __nv_bfloat16* sW2L = (__nv_bfloat16*)(sm + OFF_W2L);
        for (int i = tid; i < OUTD * (HID / 2); i += 256) {
            int n = i >> 6, p = i & 63;
            float2 f = ((const float2*)W_out)[n * 64 + p];
            __nv_bfloat16 xh = __float2bfloat16(f.x), yh = __float2bfloat16(f.y);
            sW2H[n * W2_STRIDE + 2 * p]     = xh;
            sW2H[n * W2_STRIDE + 2 * p + 1] = yh;
            sW2L[n * W2_STRIDE + 2 * p]     = __float2bfloat16(f.x - __bfloat162float(xh));
            sW2L[n * W2_STRIDE + 2 * p + 1] = __float2bfloat16(f.y - __bfloat162float(yh));
        }
    }
    if (tid < 128) {
        ((float*)(sm + OFF_BO))[tid] = b_out[tid];
        ((float*)(sm + OFF_GA))[tid] = gamma[tid];
        ((float*)(sm + OFF_BE))[tid] = beta[tid];
    }
    __syncthreads();

    float* sBO = (float*)(sm + OFF_BO);
    float* sGA = (float*)(sm + OFF_GA);
    float* sBE = (float*)(sm + OFF_BE);

    const int lane = tid & 31, warp = tid >> 5;
    const int qrow = lane >> 2, qcol = lane & 3;
    const int g = lane >> 3, r = lane & 7;
    const int lro = ((g & 2) ? 8 : 0) + r;
    const int lco = (g & 1) * 8;
    const uint32_t w1h_base = base + OFF_W1H + (uint32_t)(lro * W1_STRIDE + lco) * 2;
    const uint32_t w1l_base = base + OFF_W1L + (uint32_t)(lro * W1_STRIDE + lco) * 2;
    const uint32_t w2h_base = base + OFF_W2H + (uint32_t)(lro * W2_STRIDE + lco) * 2;
    const uint32_t w2l_base = base + OFF_W2L + (uint32_t)(lro * W2_STRIDE + lco) * 2;

    for (int tile = blockIdx.x; tile < ntiles; tile += gridDim.x) {
        const int e0w = tile * TILE + warp * 16;
        const int er0i = e0w + qrow, er1i = er0i + 8;
        const int ge0 = (er0i < E) ? er0i : (E - 1);
        const int ge1 = (er1i < E) ? er1i : (E - 1);
        const float* er0 = efeat + (size_t)ge0 * IN_DIM + 2 * qcol;
        const float* er1 = efeat + (size_t)ge1 * IN_DIM + 2 * qcol;

        // prefetch gather rows into L2 while GEMM1 runs
        const int si0 = src_idx[ge0], di0 = dst_idx[ge0];
        const int si1 = src_idx[ge1], di1 = dst_idx[ge1];
        const float* ps0 = g_src_proj + (size_t)si0 * HID + 2 * qcol;
        const float* pd0 = g_dst_proj + (size_t)di0 * HID + 2 * qcol;
        const float* ps1 = g_src_proj + (size_t)si1 * HID + 2 * qcol;
        const float* pd1 = g_dst_proj + (size_t)di1 * HID + 2 * qcol;
        asm volatile("prefetch.global.L2 [%0];" :: "l"(ps0));
        asm volatile("prefetch.global.L2 [%0];" :: "l"(pd0));
        asm volatile("prefetch.global.L2 [%0];" :: "l"(ps1));
        asm volatile("prefetch.global.L2 [%0];" :: "l"(pd1));
        asm volatile("prefetch.global.L2 [%0];" :: "l"(ps0 + 64));
        asm volatile("prefetch.global.L2 [%0];" :: "l"(pd0 + 64));
        asm volatile("prefetch.global.L2 [%0];" :: "l"(ps1 + 64));
        asm volatile("prefetch.global.L2 [%0];" :: "l"(pd1 + 64));

        // ---- A1 fragments straight from global ----
        uint32_t aH1[4][4], aL1[4][4];
        #pragma unroll
        for (int s = 0; s < 4; s++) {
            float2 f0 = *(const float2*)(er0 + 16 * s);
            float2 f1 = *(const float2*)(er1 + 16 * s);
            float2 f2 = *(const float2*)(er0 + 16 * s + 8);
            float2 f3 = *(const float2*)(er1 + 16 * s + 8);
            split_pack(f0.x, f0.y, aH1[s][0], aL1[s][0]);
            split_pack(f1.x, f1.y, aH1[s][1], aL1[s][1]);
            split_pack(f2.x, f2.y, aH1[s][2], aL1[s][2]);
            split_pack(f3.x, f3.y, aH1[s][3], aL1[s][3]);
        }

        // ---- GEMM1: 128x128x64, 3-term split, batched per k-slice ----
        float acc1[16][4];
        #pragma unroll
        for (int j = 0; j < 16; j++) { acc1[j][0]=0.f; acc1[j][1]=0.f; acc1[j][2]=0.f; acc1[j][3]=0.f; }
        #pragma unroll
        for (int s = 0; s < 4; s++) {
            uint32_t bH[8][4], bL[8][4];
            #pragma unroll
            for (int jp = 0; jp < 8; jp++)
                ldsm4(bH[jp], w1h_base + (uint32_t)(jp * 16 * W1_STRIDE + 16 * s) * 2);
            #pragma unroll
            for (int jp = 0; jp < 8; jp++) {
                mma16816(acc1[2*jp],   aH1[s], bH[jp]);
                mma16816(acc1[2*jp+1], aH1[s], bH[jp] + 2);
            }
            #pragma unroll
            for (int jp = 0; jp < 8; jp++)
                ldsm4(bL[jp], w1l_base + (uint32_t)(jp * 16 * W1_STRIDE + 16 * s) * 2);
            #pragma unroll
            for (int jp = 0; jp < 8; jp++) {
                mma16816(acc1[2*jp],   aL1[s], bH[jp]);
                mma16816(acc1[2*jp+1], aL1[s], bH[jp] + 2);
            }
            #pragma unroll
            for (int jp = 0; jp < 8; jp++) {
                mma16816(acc1[2*jp],   aH1[s], bL[jp]);
                mma16816(acc1[2*jp+1], aH1[s], bL[jp] + 2);
            }
        }

        // ---- gather + SiLU + pre-split into GEMM2 A-frags (acc1 dies here) ----
        uint32_t a2H[8][4], a2L[8][4];
        #pragma unroll
        for (int s = 0; s < 8; s++) {
            float2 a0 = *(const float2*)(ps0 + 16 * s);
            float2 b0 = *(const float2*)(pd0 + 16 * s);
            float2 c0 = *(const float2*)(ps1 + 16 * s);
            float2 d0 = *(const float2*)(pd1 + 16 * s);
            float2 a1 = *(const float2*)(ps0 + 16 * s + 8);
            float2 b1v = *(const float2*)(pd0 + 16 * s + 8);
            float2 c1 = *(const float2*)(ps1 + 16 * s + 8);
            float2 d1 = *(const float2*)(pd1 + 16 * s + 8);
            float h0 = fsilu(acc1[2*s][0]   + a0.x + b0.x);
            float h1 = fsilu(acc1[2*s][1]   + a0.y + b0.y);
            float h2 = fsilu(acc1[2*s][2]   + c0.x + d0.x);
            float h3 = fsilu(acc1[2*s][3]   + c0.y + d0.y);
            float h4 = fsilu(acc1[2*s+1][0] + a1.x + b1v.x);
            float h5 = fsilu(acc1[2*s+1][1] + a1.y + b1v.y);
            float h6 = fsilu(acc1[2*s+1][2] + c1.x + d1.x);
            float h7 = fsilu(acc1[2*s+1][3] + c1.y + d1.y);
            split_pack(h0, h1, a2H[s][0], a2L[s][0]);
            split_pack(h2, h3, a2H[s][1], a2L[s][1]);
            split_pack(h4, h5, a2H[s][2], a2L[s][2]);
            split_pack(h6, h7, a2H[s][3], a2L[s][3]);
        }

        // ---- GEMM2: 128x128x128, 3-term split, batched per k-slice ----
        float acc2[16][4];
        #pragma unroll
        for (int j = 0; j < 16; j++) { acc2[j][0]=0.f; acc2[j][1]=0.f; acc2[j][2]=0.f; acc2[j][3]=0.f; }
        #pragma unroll
        for (int s = 0; s < 8; s++) {
            uint32_t bH[8][4], bL[8][4];
            #pragma unroll
            for (int jp = 0; jp < 8; jp++)
                ldsm4(bH[jp], w2h_base + (uint32_t)(jp * 16 * W2_STRIDE + 16 * s) * 2);
            #pragma unroll
            for (int jp = 0; jp < 8; jp++) {
                mma16816(acc2[2*jp],   a2H[s], bH[jp]);
                mma16816(acc2[2*jp+1], a2H[s], bH[jp] + 2);
            }
            #pragma unroll
            for (int jp = 0; jp < 8; jp++)
                ldsm4(bL[jp], w2l_base + (uint32_t)(jp * 16 * W2_STRIDE + 16 * s) * 2);
            #pragma unroll
            for (int jp = 0; jp < 8; jp++) {
                mma16816(acc2[2*jp],   a2L[s], bH[jp]);
                mma16816(acc2[2*jp+1], a2L[s], bH[jp] + 2);
            }
            #pragma unroll
            for (int jp = 0; jp < 8; jp++) {
                mma16816(acc2[2*jp],   a2H[s], bL[jp]);
                mma16816(acc2[2*jp+1], a2H[s], bL[jp] + 2);
            }
        }

        // ---- bias + LayerNorm (quad shuffle) + store ----
        float s0 = 0.f, ss0 = 0.f, s1 = 0.f, ss1 = 0.f;
        #pragma unroll
        for (int j = 0; j < 16; j++) {
            float2 bo = *(const float2*)(sBO + 8 * j + 2 * qcol);
            acc2[j][0] += bo.x; acc2[j][1] += bo.y;
            acc2[j][2] += bo.x; acc2[j][3] += bo.y;
            s0  += acc2[j][0] + acc2[j][1];
            ss0 += acc2[j][0] * acc2[j][0] + acc2[j][1] * acc2[j][1];
            s1  += acc2[j][2] + acc2[j][3];
            ss1 += acc2[j][2] * acc2[j][2] + acc2[j][3] * acc2[j][3];
        }
        s0  += __shfl_xor_sync(0xffffffffu, s0, 1);  s0  += __shfl_xor_sync(0xffffffffu, s0, 2);
        ss0 += __shfl_xor_sync(0xffffffffu, ss0, 1); ss0 += __shfl_xor_sync(0xffffffffu, ss0, 2);
        s1  += __shfl_xor_sync(0xffffffffu, s1, 1);  s1  += __shfl_xor_sync(0xffffffffu, s1, 2);
        ss1 += __shfl_xor_sync(0xffffffffu, ss1, 1); ss1 += __shfl_xor_sync(0xffffffffu, ss1, 2);

        const float m0 = s0 * (1.0f / OUTD);
        const float v0 = ss0 * (1.0f / OUTD) - m0 * m0;
        const float i0 = rsqrtf(v0 + 1e-5f);
        const float m1 = s1 * (1.0f / OUTD);
        const float v1 = ss1 * (1.0f / OUTD) - m1 * m1;
        const float i1 = rsqrtf(v1 + 1e-5f);

        const bool st0 = (er0i < E), st1 = (er1i < E);
        float* o0 = out + (size_t)er0i * OUTD + 2 * qcol;
        float* o1 = out + (size_t)er1i * OUTD + 2 * qcol;
        #pragma unroll
        for (int j = 0; j < 16; j++) {
            float2 ga = *(const float2*)(sGA + 8 * j + 2 * qcol);
            float2 be = *(const float2*)(sBE + 8 * j + 2 * qcol);
            if (st0) {
                float2 w;
                w.x = (acc2[j][0] - m0) * i0 * ga.x + be.x;
                w.y = (acc2[j][1] - m0) * i0 * ga.y + be.y;
                *(float2*)(o0 + 8 * j) = w;
            }
            if (st1) {
                float2 w;
                w.x = (acc2[j][2] - m1) * i1 * ga.x + be.x;
                w.y = (acc2[j][3] - m1) * i1 * ga.y + be.y;
                *(float2*)(o1 + 8 * j) = w;
            }
        }
    }
}

// ---------------------------------------------------------------------------
extern "C" void kernel_launch(void* const* d_in, const int* in_sizes, int n_in,
                              void* d_out, int out_size)
{
    const float* efeat    = (const float*)d_in[0];
    const float* src_feat = (const float*)d_in[1];
    const float* dst_feat = (const float*)d_in[2];
    const int*   src_idx  = (const int*)d_in[3];
    const int*   dst_idx  = (const int*)d_in[4];
    const float* W_efeat  = (const float*)d_in[5];
    const float* W_src    = (const float*)d_in[6];
    const float* W_dst    = (const float*)d_in[7];
    const float* b1       = (const float*)d_in[8];
    const float* W_out    = (const float*)d_in[9];
    const float* b_out    = (const float*)d_in[10];
    const float* ln_gamma = (const float*)d_in[11];
    const float* ln_beta  = (const float*)d_in[12];
    float* out = (float*)d_out;

    const int E  = in_sizes[0] / IN_DIM;
    const int Nn = in_sizes[1] / IN_DIM;
    const int ntiles  = (E + TILE - 1) / TILE;
    const int ntilesN = (Nn + TILE - 1) / TILE;

    cudaFuncSetAttribute(node_mma_kernel, cudaFuncAttributeMaxDynamicSharedMemorySize, SMEM_NODE_BYTES);
    cudaFuncSetAttribute(edge_mma_kernel, cudaFuncAttributeMaxDynamicSharedMemorySize, SMEM_EDGE_BYTES);

    int nsm = 148;
    cudaDeviceGetAttribute(&nsm, cudaDevAttrMultiProcessorCount, 0);

    int gridN = 2 * ntilesN < nsm ? 2 * ntilesN : nsm;
    node_mma_kernel<<<gridN, 256, SMEM_NODE_BYTES>>>(src_feat, dst_feat, W_src, W_dst, b1, Nn, ntilesN);

    int grid = (ntiles < nsm) ? ntiles : nsm;
    edge_mma_kernel<<<grid, 256, SMEM_EDGE_BYTES>>>(efeat, src_idx, dst_idx, W_efeat, W_out,
                                                    b_out, ln_gamma, ln_beta, out, E, ntiles);
}

// round 7
// speedup vs baseline: 3.1284x; 1.1345x over previous
#include <cuda_runtime.h>
#include <cuda_bf16.h>
#include <stdint.h>
#include <math.h>

#define IN_DIM 64
#define HID    128
#define OUTD   128
#define TILE   128
#define MAXN   100000

// ------------------------- scratch (no-alloc rule) --------------------------
__device__ float g_src_proj[(size_t)MAXN * HID];
__device__ float g_dst_proj[(size_t)MAXN * HID];

// ------------------------- helpers ------------------------------------------
__device__ __forceinline__ uint32_t smem_u32(const void* p) {
    uint32_t a;
    asm("{ .reg .u64 t; cvta.to.shared.u64 t, %1; cvt.u32.u64 %0, t; }" : "=r"(a) : "l"(p));
    return a;
}
__device__ __forceinline__ void ldsm4(uint32_t* r, uint32_t addr) {
    asm volatile("ldmatrix.sync.aligned.m8n8.x4.shared.b16 {%0,%1,%2,%3}, [%4];"
                 : "=r"(r[0]), "=r"(r[1]), "=r"(r[2]), "=r"(r[3]) : "r"(addr));
}
__device__ __forceinline__ void mma16816(float* d, const uint32_t* a, const uint32_t* b) {
    asm volatile("mma.sync.aligned.m16n8k16.row.col.f32.bf16.bf16.f32 "
                 "{%0,%1,%2,%3}, {%4,%5,%6,%7}, {%8,%9}, {%0,%1,%2,%3};"
                 : "+f"(d[0]), "+f"(d[1]), "+f"(d[2]), "+f"(d[3])
                 : "r"(a[0]), "r"(a[1]), "r"(a[2]), "r"(a[3]), "r"(b[0]), "r"(b[1]));
}
__device__ __forceinline__ void mma_tf32(float* d, const uint32_t* a, uint32_t b0, uint32_t b1) {
    asm volatile("mma.sync.aligned.m16n8k8.row.col.f32.tf32.tf32.f32 "
                 "{%0,%1,%2,%3}, {%4,%5,%6,%7}, {%8,%9}, {%0,%1,%2,%3};"
                 : "+f"(d[0]), "+f"(d[1]), "+f"(d[2]), "+f"(d[3])
                 : "r"(a[0]), "r"(a[1]), "r"(a[2]), "r"(a[3]), "r"(b0), "r"(b1));
}
__device__ __forceinline__ uint32_t cvt_tf32(float f) {
    uint32_t u;
    asm("cvt.rna.tf32.f32 %0, %1;" : "=r"(u) : "f"(f));
    return u;
}
__device__ __forceinline__ void split_pack(float x, float y, uint32_t& h, uint32_t& l) {
    __nv_bfloat16 xh = __float2bfloat16(x), yh = __float2bfloat16(y);
    __nv_bfloat16 xl = __float2bfloat16(x - __bfloat162float(xh));
    __nv_bfloat16 yl = __float2bfloat16(y - __bfloat162float(yh));
    h = (uint32_t)(*(uint16_t*)&xh) | ((uint32_t)(*(uint16_t*)&yh) << 16);
    l = (uint32_t)(*(uint16_t*)&xl) | ((uint32_t)(*(uint16_t*)&yl) << 16);
}
__device__ __forceinline__ float fsilu(float x) { return x / (1.0f + __expf(-x)); }

// ------------------------- smem layouts --------------------------------------
// edge kernel: W frags in tf32 frag-stream layout
#define OFF_F1 0          // 2048 uint4 = 32768 B  : [nt(16)][s2(4)][lane(32)]
#define OFF_F2 32768      // 4096 uint4 = 65536 B  : [nt(16)][s2(8)][lane(32)]
#define OFF_BO 98304
#define OFF_GA 98816
#define OFF_BE 99328
#define SMEM_EDGE_BYTES 99840
// node kernel (bf16 3-term, unchanged)
#define W1_STRIDE 72
#define OFF_NSH 0
#define OFF_NSL 18432
#define OFF_NDH 36864
#define OFF_NDL 55296
#define OFF_NB1 73728
#define SMEM_NODE_BYTES 74240

__device__ __forceinline__ void stage_w64(const float* __restrict__ W,
                                          __nv_bfloat16* sH, __nv_bfloat16* sL, int tid, int nthr) {
    for (int i = tid; i < HID * (IN_DIM / 2); i += nthr) {
        int n = i >> 5, p = i & 31;
        float2 f = ((const float2*)W)[n * 32 + p];
        __nv_bfloat16 xh = __float2bfloat16(f.x), yh = __float2bfloat16(f.y);
        sH[n * W1_STRIDE + 2 * p]     = xh;
        sH[n * W1_STRIDE + 2 * p + 1] = yh;
        sL[n * W1_STRIDE + 2 * p]     = __float2bfloat16(f.x - __bfloat162float(xh));
        sL[n * W1_STRIDE + 2 * p + 1] = __float2bfloat16(f.y - __bfloat162float(yh));
    }
}

// ---------------------------------------------------------------------------
// Kernel 1: node projections via HMMA bf16 3-term (near-exact)
// ---------------------------------------------------------------------------
__global__ __launch_bounds__(256) void node_mma_kernel(
    const float* __restrict__ src_feat, const float* __restrict__ dst_feat,
    const float* __restrict__ W_src, const float* __restrict__ W_dst,
    const float* __restrict__ b1, int Nn, int ntilesN)
{
    extern __shared__ char smraw[];
    char* sm = smraw;
    const uint32_t base = smem_u32(smraw);
    const int tid = threadIdx.x;

    stage_w64(W_src, (__nv_bfloat16*)(sm + OFF_NSH), (__nv_bfloat16*)(sm + OFF_NSL), tid, 256);
    stage_w64(W_dst, (__nv_bfloat16*)(sm + OFF_NDH), (__nv_bfloat16*)(sm + OFF_NDL), tid, 256);
    if (tid < 128) ((float*)(sm + OFF_NB1))[tid] = b1[tid];
    __syncthreads();

    const int lane = tid & 31, warp = tid >> 5;
    const int qrow = lane >> 2, qcol = lane & 3;
    const int g = lane >> 3, r = lane & 7;
    const int lro = ((g & 2) ? 8 : 0) + r;
    const int lco = (g & 1) * 8;
    const uint32_t lmoff = (uint32_t)(lro * W1_STRIDE + lco) * 2;

    const int nitems = 2 * ntilesN;
    for (int item = blockIdx.x; item < nitems; item += gridDim.x) {
        const bool is_dst = (item >= ntilesN);
        const int tile = is_dst ? (item - ntilesN) : item;
        const float* X = is_dst ? dst_feat : src_feat;
        float* Out = is_dst ? g_dst_proj : g_src_proj;
        const uint32_t wh_base = base + (is_dst ? OFF_NDH : OFF_NSH) + lmoff;
        const uint32_t wl_base = base + (is_dst ? OFF_NDL : OFF_NSL) + lmoff;

        const int n0w = tile * TILE + warp * 16;
        const int nr0i = n0w + qrow, nr1i = nr0i + 8;
        const int gn0 = (nr0i < Nn) ? nr0i : (Nn - 1);
        const int gn1 = (nr1i < Nn) ? nr1i : (Nn - 1);
        const float* xr0 = X + (size_t)gn0 * IN_DIM + 2 * qcol;
        const float* xr1 = X + (size_t)gn1 * IN_DIM + 2 * qcol;

        uint32_t aH[4][4], aL[4][4];
        #pragma unroll
        for (int s = 0; s < 4; s++) {
            float2 f0 = *(const float2*)(xr0 + 16 * s);
            float2 f1 = *(const float2*)(xr1 + 16 * s);
            float2 f2 = *(const float2*)(xr0 + 16 * s + 8);
            float2 f3 = *(const float2*)(xr1 + 16 * s + 8);
            split_pack(f0.x, f0.y, aH[s][0], aL[s][0]);
            split_pack(f1.x, f1.y, aH[s][1], aL[s][1]);
            split_pack(f2.x, f2.y, aH[s][2], aL[s][2]);
            split_pack(f3.x, f3.y, aH[s][3], aL[s][3]);
        }

        float acc[16][4];
        #pragma unroll
        for (int j = 0; j < 16; j++) { acc[j][0]=0.f; acc[j][1]=0.f; acc[j][2]=0.f; acc[j][3]=0.f; }

        #pragma unroll
        for (int s = 0; s < 4; s++) {
            uint32_t bH[8][4], bL[8][4];
            #pragma unroll
            for (int jp = 0; jp < 8; jp++)
                ldsm4(bH[jp], wh_base + (uint32_t)(jp * 16 * W1_STRIDE + 16 * s) * 2);
            #pragma unroll
            for (int jp = 0; jp < 8; jp++) {
                mma16816(acc[2*jp],   aH[s], bH[jp]);
                mma16816(acc[2*jp+1], aH[s], bH[jp] + 2);
            }
            #pragma unroll
            for (int jp = 0; jp < 8; jp++)
                ldsm4(bL[jp], wl_base + (uint32_t)(jp * 16 * W1_STRIDE + 16 * s) * 2);
            #pragma unroll
            for (int jp = 0; jp < 8; jp++) {
                mma16816(acc[2*jp],   aL[s], bH[jp]);
                mma16816(acc[2*jp+1], aL[s], bH[jp] + 2);
            }
            #pragma unroll
            for (int jp = 0; jp < 8; jp++) {
                mma16816(acc[2*jp],   aH[s], bL[jp]);
                mma16816(acc[2*jp+1], aH[s], bL[jp] + 2);
            }
        }

        const float* sb1 = (const float*)(sm + OFF_NB1);
        const bool st0 = (nr0i < Nn), st1 = (nr1i < Nn);
        float* o0 = Out + (size_t)nr0i * HID + 2 * qcol;
        float* o1 = Out + (size_t)nr1i * HID + 2 * qcol;
        #pragma unroll
        for (int j = 0; j < 16; j++) {
            float2 bb = make_float2(0.f, 0.f);
            if (is_dst) bb = *(const float2*)(sb1 + 8 * j + 2 * qcol);
            if (st0) *(float2*)(o0 + 8 * j) = make_float2(acc[j][0] + bb.x, acc[j][1] + bb.y);
            if (st1) *(float2*)(o1 + 8 * j) = make_float2(acc[j][2] + bb.x, acc[j][3] + bb.y);
        }
    }
}

// ---------------------------------------------------------------------------
// Kernel 2: persistent TF32 edge pipeline with permuted frag-stream weights
//
//  efeat k-permutation  psi: A-frag slot (s,q,half) <-> logical col q*16+2s+half
//  h     permutation    L:   (nt,q,half)            <-> logical col q*32+2nt+half
//  => A-frags from 8 LDG.128; h stays in registers; gathers are 32 contig floats
// ---------------------------------------------------------------------------
__global__ __launch_bounds__(256) void edge_tf32_kernel(
    const float* __restrict__ efeat,
    const int* __restrict__ src_idx, const int* __restrict__ dst_idx,
    const float* __restrict__ W_efeat, const float* __restrict__ W_out,
    const float* __restrict__ b_out, const float* __restrict__ gamma,
    const float* __restrict__ beta,
    float* __restrict__ out, int E, int ntiles)
{
    extern __shared__ char smraw[];
    char* sm = smraw;
    const int tid = threadIdx.x;

    // ---- stage W1 frags: frag1[nt(16)][s2(4)][lane(32)] (uint4 = b-pairs for slices 2s2,2s2+1)
    {
        uint4* f1 = (uint4*)(sm + OFF_F1);
        for (int idx = tid; idx < 2048; idx += 256) {
            int nt = idx >> 7, rem = idx & 127;
            int s2 = rem >> 5, l = rem & 31;
            int q = l & 3, gp = l >> 2;
            int Ln = (gp >> 1) * 32 + 2 * nt + (gp & 1);      // h-row (permuted n of GEMM1)
            int col = q * 16 + 4 * s2;                         // psi-permuted k
            float4 w = *(const float4*)(W_efeat + Ln * IN_DIM + col);
            f1[idx] = make_uint4(cvt_tf32(w.x), cvt_tf32(w.y), cvt_tf32(w.z), cvt_tf32(w.w));
        }
    }
    // ---- stage W2 frags: frag2[nt(16)][s2(8)][lane(32)]
    {
        uint4* f2 = (uint4*)(sm + OFF_F2);
        for (int idx = tid; idx < 4096; idx += 256) {
            int nt = idx >> 8, rem = idx & 255;
            int s2 = rem >> 5, l = rem & 31;
            int q = l & 3, gp = l >> 2;
            int n = nt * 8 + gp;                               // output n: unpermuted
            int col = q * 32 + 4 * s2;                         // h-permuted k
            float4 w = *(const float4*)(W_out + n * HID + col);
            f2[idx] = make_uint4(cvt_tf32(w.x), cvt_tf32(w.y), cvt_tf32(w.z), cvt_tf32(w.w));
        }
    }
    if (tid < 128) {
        ((float*)(sm + OFF_BO))[tid] = b_out[tid];
        ((float*)(sm + OFF_GA))[tid] = gamma[tid];
        ((float*)(sm + OFF_BE))[tid] = beta[tid];
    }
    __syncthreads();

    const float* sBO = (const float*)(sm + OFF_BO);
    const float* sGA = (const float*)(sm + OFF_GA);
    const float* sBE = (const float*)(sm + OFF_BE);
    const uint4* f1 = (const uint4*)(sm + OFF_F1);
    const uint4* f2 = (const uint4*)(sm + OFF_F2);

    const int lane = tid & 31, warp = tid >> 5;
    const int qrow = lane >> 2, qcol = lane & 3;

    for (int tile = blockIdx.x; tile < ntiles; tile += gridDim.x) {
        const int e0w = tile * TILE + warp * 16;
        const int er0i = e0w + qrow, er1i = er0i + 8;
        const int ge0 = (er0i < E) ? er0i : (E - 1);
        const int ge1 = (er1i < E) ? er1i : (E - 1);

        // gather pointers (each thread's span = 32 contiguous floats = one 128B line)
        const int si0 = src_idx[ge0], di0 = dst_idx[ge0];
        const int si1 = src_idx[ge1], di1 = dst_idx[ge1];
        const float4* ps0 = (const float4*)(g_src_proj + (size_t)si0 * HID + qcol * 32);
        const float4* pd0 = (const float4*)(g_dst_proj + (size_t)di0 * HID + qcol * 32);
        const float4* ps1 = (const float4*)(g_src_proj + (size_t)si1 * HID + qcol * 32);
        const float4* pd1 = (const float4*)(g_dst_proj + (size_t)di1 * HID + qcol * 32);
        asm volatile("prefetch.global.L2 [%0];" :: "l"(ps0));
        asm volatile("prefetch.global.L2 [%0];" :: "l"(pd0));
        asm volatile("prefetch.global.L2 [%0];" :: "l"(ps1));
        asm volatile("prefetch.global.L2 [%0];" :: "l"(pd1));

        // ---- A1 frags: 16 contiguous floats per row (psi permutation) ----
        float eb0[16], eb1[16];
        {
            const float4* e0p = (const float4*)(efeat + (size_t)ge0 * IN_DIM + qcol * 16);
            const float4* e1p = (const float4*)(efeat + (size_t)ge1 * IN_DIM + qcol * 16);
            #pragma unroll
            for (int t = 0; t < 4; t++) {
                float4 v0 = e0p[t], v1 = e1p[t];
                eb0[4*t] = v0.x; eb0[4*t+1] = v0.y; eb0[4*t+2] = v0.z; eb0[4*t+3] = v0.w;
                eb1[4*t] = v1.x; eb1[4*t+1] = v1.y; eb1[4*t+2] = v1.z; eb1[4*t+3] = v1.w;
            }
        }
        uint32_t a1[8][4];
        #pragma unroll
        for (int s = 0; s < 8; s++) {
            a1[s][0] = cvt_tf32(eb0[2*s]);
            a1[s][1] = cvt_tf32(eb1[2*s]);
            a1[s][2] = cvt_tf32(eb0[2*s+1]);
            a1[s][3] = cvt_tf32(eb1[2*s+1]);
        }

        // ---- GEMM1: 128x128x64 tf32, groups of 4 independent accumulators ----
        float acc1[16][4];
        #pragma unroll
        for (int j = 0; j < 16; j++) { acc1[j][0]=0.f; acc1[j][1]=0.f; acc1[j][2]=0.f; acc1[j][3]=0.f; }
        #pragma unroll
        for (int s2 = 0; s2 < 4; s2++) {
            #pragma unroll
            for (int ntg = 0; ntg < 4; ntg++) {
                const int n0 = 4 * ntg;
                uint4 b0 = f1[((n0 + 0) * 4 + s2) * 32 + lane];
                uint4 b1 = f1[((n0 + 1) * 4 + s2) * 32 + lane];
                uint4 b2 = f1[((n0 + 2) * 4 + s2) * 32 + lane];
                uint4 b3 = f1[((n0 + 3) * 4 + s2) * 32 + lane];
                mma_tf32(acc1[n0+0], a1[2*s2],   b0.x, b0.y);
                mma_tf32(acc1[n0+1], a1[2*s2],   b1.x, b1.y);
                mma_tf32(acc1[n0+2], a1[2*s2],   b2.x, b2.y);
                mma_tf32(acc1[n0+3], a1[2*s2],   b3.x, b3.y);
                mma_tf32(acc1[n0+0], a1[2*s2+1], b0.z, b0.w);
                mma_tf32(acc1[n0+1], a1[2*s2+1], b1.z, b1.w);
                mma_tf32(acc1[n0+2], a1[2*s2+1], b2.z, b2.w);
                mma_tf32(acc1[n0+3], a1[2*s2+1], b3.z, b3.w);
            }
        }

        // ---- gather + SiLU + cvt to GEMM2 A-frags (h perm makes loads contiguous) ----
        uint32_t a2[16][4];
        #pragma unroll
        for (int ntp = 0; ntp < 8; ntp++) {
            float4 gs0 = ps0[ntp], gd0 = pd0[ntp];
            float4 gs1 = ps1[ntp], gd1 = pd1[ntp];
            {
                const int nt = 2 * ntp;
                float v0 = fsilu(acc1[nt][0] + gs0.x + gd0.x);   // row0, col 2nt
                float v1 = fsilu(acc1[nt][1] + gs0.y + gd0.y);   // row0, col 2nt+1
                float v2 = fsilu(acc1[nt][2] + gs1.x + gd1.x);   // row1, col 2nt
                float v3 = fsilu(acc1[nt][3] + gs1.y + gd1.y);   // row1, col 2nt+1
                a2[nt][0] = cvt_tf32(v0); a2[nt][2] = cvt_tf32(v1);
                a2[nt][1] = cvt_tf32(v2); a2[nt][3] = cvt_tf32(v3);
            }
            {
                const int nt = 2 * ntp + 1;
                float v0 = fsilu(acc1[nt][0] + gs0.z + gd0.z);
                float v1 = fsilu(acc1[nt][1] + gs0.w + gd0.w);
                float v2 = fsilu(acc1[nt][2] + gs1.z + gd1.z);
                float v3 = fsilu(acc1[nt][3] + gs1.w + gd1.w);
                a2[nt][0] = cvt_tf32(v0); a2[nt][2] = cvt_tf32(v1);
                a2[nt][1] = cvt_tf32(v2); a2[nt][3] = cvt_tf32(v3);
            }
        }

        // ---- GEMM2: 128x128x128 tf32 ----
        float acc2[16][4];
        #pragma unroll
        for (int j = 0; j < 16; j++) { acc2[j][0]=0.f; acc2[j][1]=0.f; acc2[j][2]=0.f; acc2[j][3]=0.f; }
        #pragma unroll
        for (int s2 = 0; s2 < 8; s2++) {
            #pragma unroll
            for (int ntg = 0; ntg < 4; ntg++) {
                const int n0 = 4 * ntg;
                uint4 b0 = f2[((n0 + 0) * 8 + s2) * 32 + lane];
                uint4 b1 = f2[((n0 + 1) * 8 + s2) * 32 + lane];
                uint4 b2 = f2[((n0 + 2) * 8 + s2) * 32 + lane];
                uint4 b3 = f2[((n0 + 3) * 8 + s2) * 32 + lane];
                mma_tf32(acc2[n0+0], a2[2*s2],   b0.x, b0.y);
                mma_tf32(acc2[n0+1], a2[2*s2],   b1.x, b1.y);
                mma_tf32(acc2[n0+2], a2[2*s2],   b2.x, b2.y);
                mma_tf32(acc2[n0+3], a2[2*s2],   b3.x, b3.y);
                mma_tf32(acc2[n0+0], a2[2*s2+1], b0.z, b0.w);
                mma_tf32(acc2[n0+1], a2[2*s2+1], b1.z, b1.w);
                mma_tf32(acc2[n0+2], a2[2*s2+1], b2.z, b2.w);
                mma_tf32(acc2[n0+3], a2[2*s2+1], b3.z, b3.w);
            }
        }

        // ---- bias + LayerNorm (quad shuffle) + store ----
        float s0 = 0.f, ss0 = 0.f, s1 = 0.f, ss1 = 0.f;
        #pragma unroll
        for (int j = 0; j < 16; j++) {
            float2 bo = *(const float2*)(sBO + 8 * j + 2 * qcol);
            acc2[j][0] += bo.x; acc2[j][1] += bo.y;
            acc2[j][2] += bo.x; acc2[j][3] += bo.y;
            s0  += acc2[j][0] + acc2[j][1];
            ss0 += acc2[j][0] * acc2[j][0] + acc2[j][1] * acc2[j][1];
            s1  += acc2[j][2] + acc2[j][3];
            ss1 += acc2[j][2] * acc2[j][2] + acc2[j][3] * acc2[j][3];
        }
        s0  += __shfl_xor_sync(0xffffffffu, s0, 1);  s0  += __shfl_xor_sync(0xffffffffu, s0, 2);
        ss0 += __shfl_xor_sync(0xffffffffu, ss0, 1); ss0 += __shfl_xor_sync(0xffffffffu, ss0, 2);
        s1  += __shfl_xor_sync(0xffffffffu, s1, 1);  s1  += __shfl_xor_sync(0xffffffffu, s1, 2);
        ss1 += __shfl_xor_sync(0xffffffffu, ss1, 1); ss1 += __shfl_xor_sync(0xffffffffu, ss1, 2);

        const float m0 = s0 * (1.0f / OUTD);
        const float v0 = ss0 * (1.0f / OUTD) - m0 * m0;
        const float i0 = rsqrtf(v0 + 1e-5f);
        const float m1 = s1 * (1.0f / OUTD);
        const float v1 = ss1 * (1.0f / OUTD) - m1 * m1;
        const float i1 = rsqrtf(v1 + 1e-5f);

        const bool st0 = (er0i < E), st1 = (er1i < E);
        float* o0 = out + (size_t)er0i * OUTD + 2 * qcol;
        float* o1 = out + (size_t)er1i * OUTD + 2 * qcol;
        #pragma unroll
        for (int j = 0; j < 16; j++) {
            float2 ga = *(const float2*)(sGA + 8 * j + 2 * qcol);
            float2 be = *(const float2*)(sBE + 8 * j + 2 * qcol);
            if (st0) {
                float2 w;
                w.x = (acc2[j][0] - m0) * i0 * ga.x + be.x;
                w.y = (acc2[j][1] - m0) * i0 * ga.y + be.y;
                *(float2*)(o0 + 8 * j) = w;
            }
            if (st1) {
                float2 w;
                w.x = (acc2[j][2] - m1) * i1 * ga.x + be.x;
                w.y = (acc2[j][3] - m1) * i1 * ga.y + be.y;
                *(float2*)(o1 + 8 * j) = w;
            }
        }
    }
}

// ---------------------------------------------------------------------------
extern "C" void kernel_launch(void* const* d_in, const int* in_sizes, int n_in,
                              void* d_out, int out_size)
{
    const float* efeat    = (const float*)d_in[0];
    const float* src_feat = (const float*)d_in[1];
    const float* dst_feat = (const float*)d_in[2];
    const int*   src_idx  = (const int*)d_in[3];
    const int*   dst_idx  = (const int*)d_in[4];
    const float* W_efeat  = (const float*)d_in[5];
    const float* W_src    = (const float*)d_in[6];
    const float* W_dst    = (const float*)d_in[7];
    const float* b1       = (const float*)d_in[8];
    const float* W_out    = (const float*)d_in[9];
    const float* b_out    = (const float*)d_in[10];
    const float* ln_gamma = (const float*)d_in[11];
    const float* ln_beta  = (const float*)d_in[12];
    float* out = (float*)d_out;

    const int E  = in_sizes[0] / IN_DIM;
    const int Nn = in_sizes[1] / IN_DIM;
    const int ntiles  = (E + TILE - 1) / TILE;
    const int ntilesN = (Nn + TILE - 1) / TILE;

    cudaFuncSetAttribute(node_mma_kernel, cudaFuncAttributeMaxDynamicSharedMemorySize, SMEM_NODE_BYTES);
    cudaFuncSetAttribute(edge_tf32_kernel, cudaFuncAttributeMaxDynamicSharedMemorySize, SMEM_EDGE_BYTES);

    int nsm = 148;
    cudaDeviceGetAttribute(&nsm, cudaDevAttrMultiProcessorCount, 0);

    int gridN = 2 * ntilesN < nsm ? 2 * ntilesN : nsm;
    node_mma_kernel<<<gridN, 256, SMEM_NODE_BYTES>>>(src_feat, dst_feat, W_src, W_dst, b1, Nn, ntilesN);

    int grid = (ntiles < nsm) ? ntiles : nsm;
    edge_tf32_kernel<<<grid, 256, SMEM_EDGE_BYTES>>>(efeat, src_idx, dst_idx, W_efeat, W_out,
                                                     b_out, ln_gamma, ln_beta, out, E, ntiles);
}